// round 2
// baseline (speedup 1.0000x reference)
#include <cuda_runtime.h>
#include <math.h>

#define NB   16
#define CINC 12
#define TT   16352
#define ATOM 64
#define NAC  128
#define LL   512
#define NOUT (NB*CINC*TT)

// ---------------- device scratch (no allocations allowed) ----------------
__device__ float g_mean[NB*CINC];
__device__ float g_std [NB*CINC];
__device__ float g_zraw[NB*NAC*LL];    // (16,128,512)
__device__ float g_zup [NB*NAC*LL];    // compact pooled z_q per scale (stride LL)
__device__ float g_R   [NB*NAC*LL];    // total_latent_recon accumulator
__device__ float g_shp [NAC*NAC*ATOM]; // normalized shapelets
__device__ float g_W4  [NAC*NAC*4*17]; // folded shapelet weights, scale 4
__device__ float g_W2  [NAC*NAC*2*33]; // folded shapelet weights, scale 2
__device__ float g_Wf  [NAC*3*CINC*32];// folded decoder weights
__device__ float g_part[3*512];        // l1 partials per scale

// ---------------- mean / std per (b,c) ----------------
__global__ void k_meanstd(const float* __restrict__ x) {
    int row = blockIdx.x;                 // b*CINC + c
    const float* xr = x + (size_t)row * TT;
    float s = 0.f, s2 = 0.f;
    for (int t = threadIdx.x; t < TT; t += 256) {
        float v = xr[t]; s += v; s2 += v*v;
    }
    __shared__ float ss[256], sq[256];
    ss[threadIdx.x] = s; sq[threadIdx.x] = s2;
    __syncthreads();
    for (int o = 128; o > 0; o >>= 1) {
        if (threadIdx.x < o) { ss[threadIdx.x] += ss[threadIdx.x+o]; sq[threadIdx.x] += sq[threadIdx.x+o]; }
        __syncthreads();
    }
    if (threadIdx.x == 0) {
        float m  = ss[0] / (float)TT;
        float var = sq[0] / (float)TT - m*m;
        g_mean[row] = m;
        g_std[row]  = sqrtf(var + 1e-5f);
    }
}

// ---------------- normalize shapelets ----------------
__global__ void k_shpnorm(const float* __restrict__ shapelets) {
    int warp = (blockIdx.x*256 + threadIdx.x) >> 5;
    int lane = threadIdx.x & 31;
    if (warp >= NAC*NAC) return;
    const float* src = shapelets + (size_t)warp * ATOM;
    float v0 = src[lane], v1 = src[lane+32];
    float ss = v0*v0 + v1*v1;
    #pragma unroll
    for (int o = 16; o > 0; o >>= 1) ss += __shfl_xor_sync(0xFFFFFFFFu, ss, o);
    float nrm = fmaxf(sqrtf(ss), 1e-8f);
    float inv = 1.f / nrm;
    g_shp[(size_t)warp*ATOM + lane]      = v0*inv;
    g_shp[(size_t)warp*ATOM + lane + 32] = v1*inv;
}

// ---------------- fold shapelet weights for scale S ----------------
// W[(pair*S + ph)*TP + jj] = sum_{k in [S*jj-ph, S*jj+S-1-ph] ∩ [0,64)} shp[pair][k]
__global__ void k_wfold(int S, int TP) {
    float* Wout = (S == 4) ? g_W4 : g_W2;
    int id = blockIdx.x*256 + threadIdx.x;
    int total = NAC*NAC*S*TP;
    if (id >= total) return;
    int jj   = id % TP;
    int ph   = (id / TP) % S;
    int pair = id / (TP*S);
    int k0 = S*jj - ph, k1 = k0 + S - 1;
    if (k0 < 0)  k0 = 0;
    if (k1 > 63) k1 = 63;
    float acc = 0.f;
    const float* sp = g_shp + (size_t)pair*ATOM;
    for (int k = k0; k <= k1; k++) acc += sp[k];
    Wout[id] = acc;
}

// ---------------- fold decoder weights: Wf[na][d][c][r] ----------------
__global__ void k_fold(const float* __restrict__ dec_w) {
    int id = blockIdx.x*256 + threadIdx.x;
    if (id >= NAC*3*CINC*32) return;
    int r  = id & 31;
    int c  = (id >> 5) % CINC;
    int dd = (id / (32*CINC)) % 3;
    int na = id / (32*CINC*3);
    int k0, k1;
    if (dd == 0)      { k0 = 0;      k1 = 30 - r; }   // d = -1
    else if (dd == 1) { k0 = 31 - r; k1 = 62 - r; }   // d = 0
    else              { k0 = 63 - r; k1 = 63;     }   // d = +1
    float acc = 0.f;
    const float* w = dec_w + ((size_t)c*NAC + na)*ATOM;
    for (int k = k0; k <= k1; k++) acc += w[k];
    g_Wf[((na*3 + dd)*CINC + c)*32 + r] = acc;
}

// ---------------- fused stem: strided conv + relu + 1x1 conv ----------------
// grid (64, NB), 256 threads; each block: 8 output positions l
__global__ void k_stem(const float* __restrict__ x,
                       const float* __restrict__ w1, const float* __restrict__ b1,
                       const float* __restrict__ w2, const float* __restrict__ b2,
                       const float* __restrict__ scale) {
    __shared__ float xs[CINC][288];
    __shared__ float w1s[64][65];
    __shared__ float hs[64][9];
    __shared__ float mn[CINC], isd[CINC];

    int b = blockIdx.y, l0 = blockIdx.x * 8;
    int tid = threadIdx.x;
    if (tid < CINC) { mn[tid] = g_mean[b*CINC+tid]; isd[tid] = 1.f / g_std[b*CINC+tid]; }
    __syncthreads();

    int t_start = 32*l0 - 32;
    for (int i = tid; i < CINC*288; i += 256) {
        int c = i / 288, u = i - c*288;
        int t = t_start + u;
        float v = 0.f;
        if (t >= 0 && t < TT) v = (x[((size_t)b*CINC + c)*TT + t] - mn[c]) * isd[c];
        xs[c][u] = v;
    }

    float hacc[2];
    hacc[0] = b1[tid & 63];
    hacc[1] = b1[(tid+256) & 63];
    for (int c = 0; c < CINC; c++) {
        __syncthreads();
        for (int i = tid; i < 64*64; i += 256) {
            int m = i >> 6, k = i & 63;
            w1s[m][k] = w1[((size_t)m*CINC + c)*ATOM + k];
        }
        __syncthreads();
        #pragma unroll
        for (int j = 0; j < 2; j++) {
            int idx = tid + j*256;
            int li = idx >> 6, m = idx & 63;
            float a = hacc[j];
            #pragma unroll 8
            for (int k = 0; k < 64; k++) a += xs[c][li*32 + k] * w1s[m][k];
            hacc[j] = a;
        }
    }
    __syncthreads();
    #pragma unroll
    for (int j = 0; j < 2; j++) {
        int idx = tid + j*256;
        int li = idx >> 6, m = idx & 63;
        hs[m][li] = fmaxf(hacc[j], 0.f);
    }
    __syncthreads();

    float sc = scale[0];
    #pragma unroll
    for (int j = 0; j < 4; j++) {
        int idx = tid + j*256;           // idx = a*8 + li
        int a = idx >> 3, li = idx & 7;
        float z = 0.f;
        const float* w2r = w2 + (size_t)a*64;
        #pragma unroll 8
        for (int m = 0; m < 64; m++) z += hs[m][li] * w2r[m];
        z = (z + b2[a]) * sc;
        g_zraw[((size_t)b*NAC + a)*LL + l0 + li] = z;
    }
}

// ---------------- pool residual (compact) + l1 partials ----------------
// grid 512, 256 threads. Writes z_q compactly: g_zup[row*LL + j], j in [0, LL/s)
__global__ void k_pool(int s, int first, int scaleIdx) {
    int Ls = LL / s;
    int Np = NB*NAC*Ls;
    float lsum = 0.f;
    for (int e = blockIdx.x*256 + threadIdx.x; e < Np; e += 512*256) {
        int j  = e % Ls;
        int ba = e / Ls;
        size_t base = (size_t)ba*LL + (size_t)j*s;
        float sum = 0.f;
        for (int q = 0; q < s; q++) {
            float v = g_zraw[base+q];
            if (!first) v -= g_R[base+q];
            sum += v;
        }
        float avg = sum / (float)s;
        g_zup[(size_t)ba*LL + j] = avg;
        lsum += fabsf(avg);
    }
    __shared__ float red[256];
    red[threadIdx.x] = lsum;
    __syncthreads();
    for (int o = 128; o > 0; o >>= 1) {
        if (threadIdx.x < o) red[threadIdx.x] += red[threadIdx.x+o];
        __syncthreads();
    }
    if (threadIdx.x == 0) g_part[scaleIdx*512 + blockIdx.x] = red[0];
}

// ---------------- folded shapelet conv: R (+)= conv_s(z_q, W_s) ----------------
// grid (16, NB): blockIdx.x = wtile*S + r. 256 threads, 8no x 2w register tile.
// R[no, S*w + r] (+)= sum_ni sum_jj W[no,ni,ph,jj] * zq[ni, w + q_r + jj]
template<int S, int TP>
__global__ void k_fconv(int first) {
    constexpr int ZW = TP + 32;      // Zs window per ni
    constexpr int ZR = TP + 33;      // Zs row stride
    constexpr int AR = TP + 1;       // As row stride
    constexpr int LS = LL / S;
    const float* W = (S == 4) ? g_W4 : ((S == 2) ? g_W2 : g_shp);

    extern __shared__ float smem[];
    float* Zs = smem;                // [NAC][ZR]
    float* As = smem + NAC*ZR;       // [NAC][AR]

    int b  = blockIdx.y;
    int wt = blockIdx.x / S;
    int r  = blockIdx.x % S;
    int w0 = wt * 32;
    int q_r = -(((31 - r) + S - 1) / S);      // floor((r-31)/S), r < S <= 4
    int ph  = (r - 31) - S*q_r;               // in [0, S)

    int tid = threadIdx.x;
    int tx = tid & 15, ty = tid >> 4;
    int no0 = ty * 8;
    int tbase = 2*tx;

    const float* zb = g_zup + (size_t)b*NAC*LL;
    for (int i = tid; i < NAC*ZW; i += 256) {
        int ni = i / ZW, jw = i - ni*ZW;
        int j = w0 + q_r + jw;
        Zs[ni*ZR + jw] = (j >= 0 && j < LS) ? zb[(size_t)ni*LL + j] : 0.f;
    }

    float acc[8][2];
    #pragma unroll
    for (int i = 0; i < 8; i++) { acc[i][0] = 0.f; acc[i][1] = 0.f; }

    for (int ni = 0; ni < NAC; ni++) {
        __syncthreads();
        for (int i = tid; i < NAC*TP; i += 256) {
            int no = i / TP, jj = i - no*TP;
            As[no*AR + jj] = W[((size_t)(no*NAC + ni)*S + ph)*TP + jj];
        }
        __syncthreads();
        const float* zrow = Zs + ni*ZR + tbase;
        #pragma unroll 4
        for (int jj = 0; jj < TP; jj++) {
            float z0 = zrow[jj];
            float z1 = zrow[jj+1];
            #pragma unroll
            for (int i = 0; i < 8; i++) {
                float a = As[(no0+i)*AR + jj];
                acc[i][0] += a*z0;
                acc[i][1] += a*z1;
            }
        }
    }

    float* Rb = g_R + (size_t)b*NAC*LL;
    #pragma unroll
    for (int i = 0; i < 8; i++) {
        #pragma unroll
        for (int j = 0; j < 2; j++) {
            int no = no0 + i;
            int t  = S*(w0 + tbase + j) + r;
            if (first) Rb[(size_t)no*LL + t] = acc[i][j];
            else       Rb[(size_t)no*LL + t] += acc[i][j];
        }
    }
}

// ---------------- decoder with folded weights + denorm ----------------
// grid (32 p-tiles, NB), 384 threads (= 12 warps, warp id == channel c)
__global__ void k_dec(const float* __restrict__ dec_b, float* __restrict__ out) {
    __shared__ float Rs[NAC][19];
    int b  = blockIdx.y;
    int p0 = blockIdx.x * 16;
    int tid = threadIdx.x;
    int r = tid & 31, c = tid >> 5;

    const float* Rb = g_R + (size_t)b*NAC*LL;
    for (int i = tid; i < NAC*18; i += 384) {
        int na = i / 18, pp = i - na*18;
        int p = p0 - 1 + pp;
        Rs[na][pp] = (p >= 0 && p < LL) ? Rb[(size_t)na*LL + p] : 0.f;
    }
    __syncthreads();

    float acc[16];
    #pragma unroll
    for (int i = 0; i < 16; i++) acc[i] = 0.f;

    for (int na = 0; na < NAC; na++) {
        const float* wf = g_Wf + ((size_t)na*3)*CINC*32 + c*32 + r;
        float w0 = wf[0];
        float w1 = wf[CINC*32];
        float w2 = wf[2*CINC*32];
        #pragma unroll
        for (int pl = 0; pl < 16; pl++)
            acc[pl] += w0*Rs[na][pl] + w1*Rs[na][pl+1] + w2*Rs[na][pl+2];
    }

    float sd  = g_std [b*CINC + c];
    float mnv = g_mean[b*CINC + c];
    float db  = dec_b[c];
    #pragma unroll
    for (int pl = 0; pl < 16; pl++) {
        int p = p0 + pl;
        if (p < 511) {
            int t = p*32 + r;
            out[((size_t)b*CINC + c)*TT + t] = (acc[pl] + db)*sd + mnv;
        }
    }
}

// ---------------- finalize scalars (deterministic, fixed-order) ----------------
__global__ void k_final(float* __restrict__ out, int out_size) {
    if (blockIdx.x != 0 || threadIdx.x != 0) return;
    float tot = 0.f;
    const float cnt[3] = { (float)(NB*NAC*(LL/4)), (float)(NB*NAC*(LL/2)), (float)(NB*NAC*LL) };
    for (int sIdx = 0; sIdx < 3; sIdx++) {
        float ssum = 0.f;
        for (int i = 0; i < 512; i++) ssum += g_part[sIdx*512 + i];
        tot += ssum / cnt[sIdx];
    }
    if (out_size > NOUT)     out[NOUT]     = 0.f;          // total_vq_loss
    if (out_size > NOUT + 1) out[NOUT + 1] = tot * 0.01f;  // total_l1 * SPARSITY_WEIGHT
}

// ---------------- launch ----------------
extern "C" void kernel_launch(void* const* d_in, const int* in_sizes, int n_in,
                              void* d_out, int out_size) {
    const float* x        = (const float*)d_in[0];
    const float* stem_w1  = (const float*)d_in[1];
    const float* stem_b1  = (const float*)d_in[2];
    const float* stem_w2  = (const float*)d_in[3];
    const float* stem_b2  = (const float*)d_in[4];
    const float* stem_sc  = (const float*)d_in[5];
    const float* shapelet = (const float*)d_in[6];
    const float* dec_w    = (const float*)d_in[7];
    const float* dec_b    = (const float*)d_in[8];
    float* out = (float*)d_out;

    const int SM4 = (NAC*(17+33) + NAC*(17+1)) * (int)sizeof(float); // Zs[128][50]+As[128][18]
    const int SM2 = (NAC*(33+33) + NAC*(33+1)) * (int)sizeof(float); // Zs[128][66]+As[128][34]
    const int SM1 = (NAC*(64+33) + NAC*(64+1)) * (int)sizeof(float); // Zs[128][97]+As[128][65]
    cudaFuncSetAttribute(k_fconv<4,17>, cudaFuncAttributeMaxDynamicSharedMemorySize, SM4);
    cudaFuncSetAttribute(k_fconv<2,33>, cudaFuncAttributeMaxDynamicSharedMemorySize, SM2);
    cudaFuncSetAttribute(k_fconv<1,64>, cudaFuncAttributeMaxDynamicSharedMemorySize, SM1);

    k_meanstd<<<NB*CINC, 256>>>(x);
    k_shpnorm<<<(NAC*NAC*32 + 255)/256/1 /*2048*/, 256>>>(shapelet);
    k_wfold<<<(NAC*NAC*4*17 + 255)/256, 256>>>(4, 17);
    k_wfold<<<(NAC*NAC*2*33 + 255)/256, 256>>>(2, 33);
    k_fold<<<(NAC*3*CINC*32 + 255)/256, 256>>>(dec_w);
    k_stem<<<dim3(64, NB), 256>>>(x, stem_w1, stem_b1, stem_w2, stem_b2, stem_sc);

    // scale 4 (first: residual = z_raw, R = rec)
    k_pool<<<512, 256>>>(4, 1, 0);
    k_fconv<4,17><<<dim3(16, NB), 256, SM4>>>(1);
    // scale 2
    k_pool<<<512, 256>>>(2, 0, 1);
    k_fconv<2,33><<<dim3(16, NB), 256, SM2>>>(0);
    // scale 1
    k_pool<<<512, 256>>>(1, 0, 2);
    k_fconv<1,64><<<dim3(16, NB), 256, SM1>>>(0);

    k_dec<<<dim3(32, NB), 384>>>(dec_b, out);
    k_final<<<1, 32>>>(out, out_size);
}

// round 6
// speedup vs baseline: 1.5053x; 1.5053x over previous
#include <cuda_runtime.h>
#include <math.h>

#define NB   16
#define CINC 12
#define TT   16352
#define ATOM 64
#define NAC  128
#define LL   512
#define NOUT (NB*CINC*TT)

// ---------------- device scratch (no allocations allowed) ----------------
__device__ float g_mean[NB*CINC];
__device__ float g_std [NB*CINC];
__device__ float g_zraw[NB*NAC*LL];     // (16,128,512)
__device__ float g_zup [NB*NAC*LL];     // compact pooled z_q per scale (stride LL)
__device__ float g_R   [NB*NAC*LL];     // total_latent_recon accumulator
__device__ float g_W1  [NAC*1*64*NAC];  // folded weights S=1: [ni][ph=1][jj][no]
__device__ float g_W2  [NAC*2*33*NAC];  // folded weights S=2: [ni][ph][jj][no]
__device__ float g_W4  [NAC*4*17*NAC];  // folded weights S=4: [ni][ph][jj][no]
__device__ float g_Wf  [NAC*3*CINC*32]; // folded decoder weights
__device__ float g_part[3*512];         // l1 partials per scale

// ---------------- packed f32x2 helpers ----------------
__device__ __forceinline__ void ffma2(unsigned long long &d, unsigned long long a, unsigned long long b) {
    asm("fma.rn.f32x2 %0, %1, %2, %0;" : "+l"(d) : "l"(a), "l"(b));
}
__device__ __forceinline__ unsigned long long pack2(float lo, float hi) {
    unsigned long long r;
    asm("mov.b64 %0, {%1, %2};" : "=l"(r) : "f"(lo), "f"(hi));
    return r;
}
__device__ __forceinline__ float2 unpack2(unsigned long long v) {
    float2 r;
    asm("mov.b64 {%0, %1}, %2;" : "=f"(r.x), "=f"(r.y) : "l"(v));
    return r;
}

// ---------------- mean / std per (b,c) ----------------
__global__ void k_meanstd(const float* __restrict__ x) {
    int row = blockIdx.x;                 // b*CINC + c
    const float* xr = x + (size_t)row * TT;
    float s = 0.f, s2 = 0.f;
    for (int t = threadIdx.x; t < TT; t += 256) {
        float v = xr[t]; s += v; s2 += v*v;
    }
    __shared__ float ss[256], sq[256];
    ss[threadIdx.x] = s; sq[threadIdx.x] = s2;
    __syncthreads();
    for (int o = 128; o > 0; o >>= 1) {
        if (threadIdx.x < o) { ss[threadIdx.x] += ss[threadIdx.x+o]; sq[threadIdx.x] += sq[threadIdx.x+o]; }
        __syncthreads();
    }
    if (threadIdx.x == 0) {
        float m  = ss[0] / (float)TT;
        float var = sq[0] / (float)TT - m*m;
        g_mean[row] = m;
        g_std[row]  = sqrtf(var + 1e-5f);
    }
}

// ---------------- prep: normalize shapelets + build all folded, TRANSPOSED weights ----
// grid NAC (one block per ni), 256 threads.
// raw[no][k] = shapelets[no][ni][k]; inv[no] = 1/clip(||raw[no]||,1e-8)
// W_S[((ni*S + ph)*TP + jj)*NAC + no] = inv[no] * sum_{k in [S*jj-ph, S*jj+S-1-ph] ∩ [0,64)} raw[no][k]
__global__ void k_prep(const float* __restrict__ shapelets) {
    __shared__ float raw[NAC][ATOM + 1];
    __shared__ float inv[NAC];
    int ni = blockIdx.x;
    int tid = threadIdx.x;

    for (int i = tid; i < NAC*ATOM; i += 256) {
        int no = i >> 6, k = i & 63;
        raw[no][k] = shapelets[((size_t)no*NAC + ni)*ATOM + k];
    }
    __syncthreads();
    if (tid < NAC) {
        float ssum = 0.f;
        #pragma unroll 8
        for (int k = 0; k < ATOM; k++) { float v = raw[tid][k]; ssum += v*v; }
        inv[tid] = 1.f / fmaxf(sqrtf(ssum), 1e-8f);
    }
    __syncthreads();

    // S = 1 (TP=64, ph=0): plain transposed normalized copy
    for (int i = tid; i < 64*NAC; i += 256) {
        int no = i & 127, jj = i >> 7;
        g_W1[((size_t)ni*64 + jj)*NAC + no] = raw[no][jj] * inv[no];
    }
    // S = 2 (TP=33, ph in {0,1})
    for (int i = tid; i < 2*33*NAC; i += 256) {
        int no = i & 127;
        int rest = i >> 7;
        int jj = rest % 33, ph = rest / 33;
        int k0 = 2*jj - ph, k1 = k0 + 1;
        if (k0 < 0)  k0 = 0;
        if (k1 > 63) k1 = 63;
        float acc = 0.f;
        for (int k = k0; k <= k1; k++) acc += raw[no][k];
        g_W2[((size_t)(ni*2 + ph)*33 + jj)*NAC + no] = acc * inv[no];
    }
    // S = 4 (TP=17, ph in {0..3})
    for (int i = tid; i < 4*17*NAC; i += 256) {
        int no = i & 127;
        int rest = i >> 7;
        int jj = rest % 17, ph = rest / 17;
        int k0 = 4*jj - ph, k1 = k0 + 3;
        if (k0 < 0)  k0 = 0;
        if (k1 > 63) k1 = 63;
        float acc = 0.f;
        for (int k = k0; k <= k1; k++) acc += raw[no][k];
        g_W4[((size_t)(ni*4 + ph)*17 + jj)*NAC + no] = acc * inv[no];
    }
}

// ---------------- fold decoder weights: Wf[na][d][c][r] ----------------
__global__ void k_fold(const float* __restrict__ dec_w) {
    int id = blockIdx.x*256 + threadIdx.x;
    if (id >= NAC*3*CINC*32) return;
    int r  = id & 31;
    int c  = (id >> 5) % CINC;
    int dd = (id / (32*CINC)) % 3;
    int na = id / (32*CINC*3);
    int k0, k1;
    if (dd == 0)      { k0 = 0;      k1 = 30 - r; }   // d = -1
    else if (dd == 1) { k0 = 31 - r; k1 = 62 - r; }   // d = 0
    else              { k0 = 63 - r; k1 = 63;     }   // d = +1
    float acc = 0.f;
    const float* w = dec_w + ((size_t)c*NAC + na)*ATOM;
    for (int k = k0; k <= k1; k++) acc += w[k];
    g_Wf[((na*3 + dd)*CINC + c)*32 + r] = acc;
}

// ---------------- fused stem: strided conv + relu + 1x1 conv ----------------
// grid (64, NB), 256 threads; each block: 8 output positions l
__global__ void k_stem(const float* __restrict__ x,
                       const float* __restrict__ w1, const float* __restrict__ b1,
                       const float* __restrict__ w2, const float* __restrict__ b2,
                       const float* __restrict__ scale) {
    __shared__ float xs[CINC][288];
    __shared__ float w1s[64][65];
    __shared__ float hs[64][9];
    __shared__ float mn[CINC], isd[CINC];

    int b = blockIdx.y, l0 = blockIdx.x * 8;
    int tid = threadIdx.x;
    if (tid < CINC) { mn[tid] = g_mean[b*CINC+tid]; isd[tid] = 1.f / g_std[b*CINC+tid]; }
    __syncthreads();

    int t_start = 32*l0 - 32;
    for (int i = tid; i < CINC*288; i += 256) {
        int c = i / 288, u = i - c*288;
        int t = t_start + u;
        float v = 0.f;
        if (t >= 0 && t < TT) v = (x[((size_t)b*CINC + c)*TT + t] - mn[c]) * isd[c];
        xs[c][u] = v;
    }

    float hacc[2];
    hacc[0] = b1[tid & 63];
    hacc[1] = b1[(tid+256) & 63];
    for (int c = 0; c < CINC; c++) {
        __syncthreads();
        for (int i = tid; i < 64*64; i += 256) {
            int m = i >> 6, k = i & 63;
            w1s[m][k] = w1[((size_t)m*CINC + c)*ATOM + k];
        }
        __syncthreads();
        #pragma unroll
        for (int j = 0; j < 2; j++) {
            int idx = tid + j*256;
            int li = idx >> 6, m = idx & 63;
            float a = hacc[j];
            #pragma unroll 8
            for (int k = 0; k < 64; k++) a += xs[c][li*32 + k] * w1s[m][k];
            hacc[j] = a;
        }
    }
    __syncthreads();
    #pragma unroll
    for (int j = 0; j < 2; j++) {
        int idx = tid + j*256;
        int li = idx >> 6, m = idx & 63;
        hs[m][li] = fmaxf(hacc[j], 0.f);
    }
    __syncthreads();

    float sc = scale[0];
    #pragma unroll
    for (int j = 0; j < 4; j++) {
        int idx = tid + j*256;           // idx = a*8 + li
        int a = idx >> 3, li = idx & 7;
        float z = 0.f;
        const float* w2r = w2 + (size_t)a*64;
        #pragma unroll 8
        for (int m = 0; m < 64; m++) z += hs[m][li] * w2r[m];
        z = (z + b2[a]) * sc;
        g_zraw[((size_t)b*NAC + a)*LL + l0 + li] = z;
    }
}

// ---------------- pool residual (compact) + l1 partials ----------------
// grid 512, 256 threads. Writes z_q compactly: g_zup[row*LL + j], j in [0, LL/s)
__global__ void k_pool(int s, int first, int scaleIdx) {
    int Ls = LL / s;
    int Np = NB*NAC*Ls;
    float lsum = 0.f;
    for (int e = blockIdx.x*256 + threadIdx.x; e < Np; e += 512*256) {
        int j  = e % Ls;
        int ba = e / Ls;
        size_t base = (size_t)ba*LL + (size_t)j*s;
        float sum = 0.f;
        for (int q = 0; q < s; q++) {
            float v = g_zraw[base+q];
            if (!first) v -= g_R[base+q];
            sum += v;
        }
        float avg = sum / (float)s;
        g_zup[(size_t)ba*LL + j] = avg;
        lsum += fabsf(avg);
    }
    __shared__ float red[256];
    red[threadIdx.x] = lsum;
    __syncthreads();
    for (int o = 128; o > 0; o >>= 1) {
        if (threadIdx.x < o) red[threadIdx.x] += red[threadIdx.x+o];
        __syncthreads();
    }
    if (threadIdx.x == 0) g_part[scaleIdx*512 + blockIdx.x] = red[0];
}

// ---------------- folded shapelet conv with packed f32x2 FMA ----------------
// grid (16, NB): blockIdx.x = wtile*S + r. 256 threads.
// Register tile per thread: 8 no (4 packed pairs) x 2 w.
// R[no, S*w + r] (+)= sum_ni sum_jj W_S[ni,ph,jj,no] * zq[ni, w + q_r + jj]
template<int S, int TP>
__global__ void k_fconv(int first) {
    constexpr int ZW = TP + 32;      // Zs window per ni
    constexpr int ZR = TP + 33;      // Zs row stride
    constexpr int LS = LL / S;
    const float* W = (S == 4) ? g_W4 : ((S == 2) ? g_W2 : g_W1);

    extern __shared__ float smem[];
    float* Zs = smem;                // [NAC][ZR]
    float* As = smem + NAC*ZR;       // [TP][NAC]  (no-contiguous rows)

    int b  = blockIdx.y;
    int wt = blockIdx.x / S;
    int r  = blockIdx.x % S;
    int w0 = wt * 32;
    int q_r = -(((31 - r) + S - 1) / S);      // floor((r-31)/S), r < S <= 4
    int ph  = (r - 31) - S*q_r;               // in [0, S)

    int tid = threadIdx.x;
    int tx = tid & 15, ty = tid >> 4;
    int no0 = ty * 8;
    int tbase = 2*tx;

    const float* zb = g_zup + (size_t)b*NAC*LL;
    for (int i = tid; i < NAC*ZW; i += 256) {
        int ni = i / ZW, jw = i - ni*ZW;
        int j = w0 + q_r + jw;
        Zs[ni*ZR + jw] = (j >= 0 && j < LS) ? zb[(size_t)ni*LL + j] : 0.f;
    }

    unsigned long long acc2[4][2];
    #pragma unroll
    for (int p = 0; p < 4; p++) { acc2[p][0] = pack2(0.f, 0.f); acc2[p][1] = pack2(0.f, 0.f); }

    for (int ni = 0; ni < NAC; ni++) {
        __syncthreads();
        {
            const float4* src = (const float4*)(W + ((size_t)(ni*S + ph)*TP)*NAC);
            float4* dst = (float4*)As;
            for (int i = tid; i < TP*NAC/4; i += 256) dst[i] = src[i];
        }
        __syncthreads();
        const float* zrow = Zs + ni*ZR + tbase;
        #pragma unroll 4
        for (int jj = 0; jj < TP; jj++) {
            float z0s = zrow[jj];
            float z1s = zrow[jj+1];
            unsigned long long z0 = pack2(z0s, z0s);
            unsigned long long z1 = pack2(z1s, z1s);
            const unsigned long long* arow = (const unsigned long long*)(As + jj*NAC + no0);
            #pragma unroll
            for (int p = 0; p < 4; p++) {
                unsigned long long a2 = arow[p];
                ffma2(acc2[p][0], a2, z0);
                ffma2(acc2[p][1], a2, z1);
            }
        }
    }

    float* Rb = g_R + (size_t)b*NAC*LL;
    #pragma unroll
    for (int p = 0; p < 4; p++) {
        #pragma unroll
        for (int j = 0; j < 2; j++) {
            float2 v = unpack2(acc2[p][j]);
            int no = no0 + 2*p;
            int t  = S*(w0 + tbase + j) + r;
            if (first) {
                Rb[(size_t)no*LL + t]     = v.x;
                Rb[(size_t)(no+1)*LL + t] = v.y;
            } else {
                Rb[(size_t)no*LL + t]     += v.x;
                Rb[(size_t)(no+1)*LL + t] += v.y;
            }
        }
    }
}

// ---------------- decoder with folded weights + denorm ----------------
// grid (32 p-tiles, NB), 384 threads (= 12 warps, warp id == channel c)
__global__ void k_dec(const float* __restrict__ dec_b, float* __restrict__ out) {
    __shared__ float Rs[NAC][19];
    int b  = blockIdx.y;
    int p0 = blockIdx.x * 16;
    int tid = threadIdx.x;
    int r = tid & 31, c = tid >> 5;

    const float* Rb = g_R + (size_t)b*NAC*LL;
    for (int i = tid; i < NAC*18; i += 384) {
        int na = i / 18, pp = i - na*18;
        int p = p0 - 1 + pp;
        Rs[na][pp] = (p >= 0 && p < LL) ? Rb[(size_t)na*LL + p] : 0.f;
    }
    __syncthreads();

    float acc[16];
    #pragma unroll
    for (int i = 0; i < 16; i++) acc[i] = 0.f;

    for (int na = 0; na < NAC; na++) {
        const float* wf = g_Wf + ((size_t)na*3)*CINC*32 + c*32 + r;
        float w0 = wf[0];
        float w1 = wf[CINC*32];
        float w2 = wf[2*CINC*32];
        #pragma unroll
        for (int pl = 0; pl < 16; pl++)
            acc[pl] += w0*Rs[na][pl] + w1*Rs[na][pl+1] + w2*Rs[na][pl+2];
    }

    float sd  = g_std [b*CINC + c];
    float mnv = g_mean[b*CINC + c];
    float db  = dec_b[c];
    #pragma unroll
    for (int pl = 0; pl < 16; pl++) {
        int p = p0 + pl;
        if (p < 511) {
            int t = p*32 + r;
            out[((size_t)b*CINC + c)*TT + t] = (acc[pl] + db)*sd + mnv;
        }
    }
}

// ---------------- finalize scalars (deterministic, fixed-order) ----------------
__global__ void k_final(float* __restrict__ out, int out_size) {
    if (blockIdx.x != 0 || threadIdx.x != 0) return;
    float tot = 0.f;
    const float cnt[3] = { (float)(NB*NAC*(LL/4)), (float)(NB*NAC*(LL/2)), (float)(NB*NAC*LL) };
    for (int sIdx = 0; sIdx < 3; sIdx++) {
        float ssum = 0.f;
        for (int i = 0; i < 512; i++) ssum += g_part[sIdx*512 + i];
        tot += ssum / cnt[sIdx];
    }
    if (out_size > NOUT)     out[NOUT]     = 0.f;          // total_vq_loss
    if (out_size > NOUT + 1) out[NOUT + 1] = tot * 0.01f;  // total_l1 * SPARSITY_WEIGHT
}

// ---------------- launch ----------------
extern "C" void kernel_launch(void* const* d_in, const int* in_sizes, int n_in,
                              void* d_out, int out_size) {
    const float* x        = (const float*)d_in[0];
    const float* stem_w1  = (const float*)d_in[1];
    const float* stem_b1  = (const float*)d_in[2];
    const float* stem_w2  = (const float*)d_in[3];
    const float* stem_b2  = (const float*)d_in[4];
    const float* stem_sc  = (const float*)d_in[5];
    const float* shapelet = (const float*)d_in[6];
    const float* dec_w    = (const float*)d_in[7];
    const float* dec_b    = (const float*)d_in[8];
    float* out = (float*)d_out;

    const int SM4 = (NAC*(17+33) + 17*NAC) * (int)sizeof(float); // Zs[128][50]+As[17][128]
    const int SM2 = (NAC*(33+33) + 33*NAC) * (int)sizeof(float); // Zs[128][66]+As[33][128]
    const int SM1 = (NAC*(64+33) + 64*NAC) * (int)sizeof(float); // Zs[128][97]+As[64][128]
    cudaFuncSetAttribute(k_fconv<4,17>, cudaFuncAttributeMaxDynamicSharedMemorySize, SM4);
    cudaFuncSetAttribute(k_fconv<2,33>, cudaFuncAttributeMaxDynamicSharedMemorySize, SM2);
    cudaFuncSetAttribute(k_fconv<1,64>, cudaFuncAttributeMaxDynamicSharedMemorySize, SM1);

    k_meanstd<<<NB*CINC, 256>>>(x);
    k_prep<<<NAC, 256>>>(shapelet);
    k_fold<<<(NAC*3*CINC*32 + 255)/256, 256>>>(dec_w);
    k_stem<<<dim3(64, NB), 256>>>(x, stem_w1, stem_b1, stem_w2, stem_b2, stem_sc);

    // scale 4 (first: residual = z_raw, R = rec)
    k_pool<<<512, 256>>>(4, 1, 0);
    k_fconv<4,17><<<dim3(16, NB), 256, SM4>>>(1);
    // scale 2
    k_pool<<<512, 256>>>(2, 0, 1);
    k_fconv<2,33><<<dim3(16, NB), 256, SM2>>>(0);
    // scale 1
    k_pool<<<512, 256>>>(1, 0, 2);
    k_fconv<1,64><<<dim3(16, NB), 256, SM1>>>(0);

    k_dec<<<dim3(32, NB), 384>>>(dec_b, out);
    k_final<<<1, 32>>>(out, out_size);
}

// round 8
// speedup vs baseline: 1.6771x; 1.1142x over previous
#include <cuda_runtime.h>
#include <math.h>

#define NB   16
#define CINC 12
#define TT   16352
#define ATOM 64
#define NAC  128
#define LL   512
#define NOUT (NB*CINC*TT)

// ---------------- device scratch (no allocations allowed) ----------------
__device__ float g_mean[NB*CINC];
__device__ float g_std [NB*CINC];
__device__ float g_zraw[NB*NAC*LL];     // (16,128,512)
__device__ float g_zup [NB*NAC*LL];     // compact pooled z_q per scale (stride LL)
__device__ float g_R   [NB*NAC*LL];     // total_latent_recon accumulator
__device__ float g_W1  [NAC*1*64*NAC];  // folded weights S=1: [ni][ph=1][jj][no]
__device__ float g_W2  [NAC*2*33*NAC];  // folded weights S=2: [ni][ph][jj][no]
__device__ float g_W4  [NAC*4*17*NAC];  // folded weights S=4: [ni][ph][jj][no]
__device__ float g_Wf  [NAC*3*CINC*32]; // folded decoder weights
__device__ float g_part[3*512];         // l1 partials per scale

// ---------------- packed f32x2 helpers ----------------
__device__ __forceinline__ void ffma2(unsigned long long &d, unsigned long long a, unsigned long long b) {
    asm("fma.rn.f32x2 %0, %1, %2, %0;" : "+l"(d) : "l"(a), "l"(b));
}
__device__ __forceinline__ unsigned long long pack2(float lo, float hi) {
    unsigned long long r;
    asm("mov.b64 %0, {%1, %2};" : "=l"(r) : "f"(lo), "f"(hi));
    return r;
}
__device__ __forceinline__ float2 unpack2(unsigned long long v) {
    float2 r;
    asm("mov.b64 {%0, %1}, %2;" : "=f"(r.x), "=f"(r.y) : "l"(v));
    return r;
}

// ---------------- mean / std per (b,c) ----------------
__global__ void k_meanstd(const float* __restrict__ x) {
    int row = blockIdx.x;                 // b*CINC + c
    const float* xr = x + (size_t)row * TT;
    float s = 0.f, s2 = 0.f;
    for (int t = threadIdx.x; t < TT; t += 256) {
        float v = xr[t]; s += v; s2 += v*v;
    }
    __shared__ float ss[256], sq[256];
    ss[threadIdx.x] = s; sq[threadIdx.x] = s2;
    __syncthreads();
    for (int o = 128; o > 0; o >>= 1) {
        if (threadIdx.x < o) { ss[threadIdx.x] += ss[threadIdx.x+o]; sq[threadIdx.x] += sq[threadIdx.x+o]; }
        __syncthreads();
    }
    if (threadIdx.x == 0) {
        float m  = ss[0] / (float)TT;
        float var = sq[0] / (float)TT - m*m;
        g_mean[row] = m;
        g_std[row]  = sqrtf(var + 1e-5f);
    }
}

// ---------------- prep: normalize shapelets + build all folded, TRANSPOSED weights ----
__global__ void k_prep(const float* __restrict__ shapelets) {
    __shared__ float raw[NAC][ATOM + 1];
    __shared__ float inv[NAC];
    int ni = blockIdx.x;
    int tid = threadIdx.x;

    for (int i = tid; i < NAC*ATOM; i += 256) {
        int no = i >> 6, k = i & 63;
        raw[no][k] = shapelets[((size_t)no*NAC + ni)*ATOM + k];
    }
    __syncthreads();
    if (tid < NAC) {
        float ssum = 0.f;
        #pragma unroll 8
        for (int k = 0; k < ATOM; k++) { float v = raw[tid][k]; ssum += v*v; }
        inv[tid] = 1.f / fmaxf(sqrtf(ssum), 1e-8f);
    }
    __syncthreads();

    // S = 1 (TP=64, ph=0)
    for (int i = tid; i < 64*NAC; i += 256) {
        int no = i & 127, jj = i >> 7;
        g_W1[((size_t)ni*64 + jj)*NAC + no] = raw[no][jj] * inv[no];
    }
    // S = 2 (TP=33)
    for (int i = tid; i < 2*33*NAC; i += 256) {
        int no = i & 127;
        int rest = i >> 7;
        int jj = rest % 33, ph = rest / 33;
        int k0 = 2*jj - ph, k1 = k0 + 1;
        if (k0 < 0)  k0 = 0;
        if (k1 > 63) k1 = 63;
        float acc = 0.f;
        for (int k = k0; k <= k1; k++) acc += raw[no][k];
        g_W2[((size_t)(ni*2 + ph)*33 + jj)*NAC + no] = acc * inv[no];
    }
    // S = 4 (TP=17)
    for (int i = tid; i < 4*17*NAC; i += 256) {
        int no = i & 127;
        int rest = i >> 7;
        int jj = rest % 17, ph = rest / 17;
        int k0 = 4*jj - ph, k1 = k0 + 3;
        if (k0 < 0)  k0 = 0;
        if (k1 > 63) k1 = 63;
        float acc = 0.f;
        for (int k = k0; k <= k1; k++) acc += raw[no][k];
        g_W4[((size_t)(ni*4 + ph)*17 + jj)*NAC + no] = acc * inv[no];
    }
}

// ---------------- fold decoder weights: Wf[na][d][c][r] ----------------
__global__ void k_fold(const float* __restrict__ dec_w) {
    int id = blockIdx.x*256 + threadIdx.x;
    if (id >= NAC*3*CINC*32) return;
    int r  = id & 31;
    int c  = (id >> 5) % CINC;
    int dd = (id / (32*CINC)) % 3;
    int na = id / (32*CINC*3);
    int k0, k1;
    if (dd == 0)      { k0 = 0;      k1 = 30 - r; }
    else if (dd == 1) { k0 = 31 - r; k1 = 62 - r; }
    else              { k0 = 63 - r; k1 = 63;     }
    float acc = 0.f;
    const float* w = dec_w + ((size_t)c*NAC + na)*ATOM;
    for (int k = k0; k <= k1; k++) acc += w[k];
    g_Wf[((na*3 + dd)*CINC + c)*32 + r] = acc;
}

// ---------------- fused stem: strided conv + relu + 1x1 conv (FFMA2, k-split) ----------------
// grid (64, NB), 256 threads; each block: 8 output positions l.
// Thread = (khalf, li, mq): khalf = tid>>7 handles k in [khalf*32, khalf*32+32);
// li = (tid>>4)&7; mq = tid&15 -> m in [4mq, 4mq+4). Partials combined in smem.
__global__ void k_stem(const float* __restrict__ x,
                       const float* __restrict__ w1, const float* __restrict__ b1,
                       const float* __restrict__ w2, const float* __restrict__ b2,
                       const float* __restrict__ scale) {
    __shared__ float xs[CINC][288];
    __shared__ float w1t[64][68];    // [k][m], row stride 68 floats (16B-aligned rows)
    __shared__ float hp[2][64][9];   // per-khalf partial h
    __shared__ float hs[64][9];
    __shared__ float mn[CINC], isd[CINC];

    int b = blockIdx.y, l0 = blockIdx.x * 8;
    int tid = threadIdx.x;
    int half = tid >> 7;         // k-half
    int hid  = tid & 127;
    int li   = hid >> 4;         // 0..7
    int mq   = hid & 15;         // m0 = 4*mq
    int kbase = half * 32;

    if (tid < CINC) { mn[tid] = g_mean[b*CINC+tid]; isd[tid] = 1.f / g_std[b*CINC+tid]; }
    __syncthreads();

    int t_start = 32*l0 - 32;
    for (int i = tid; i < CINC*288; i += 256) {
        int c = i / 288, u = i - c*288;
        int t = t_start + u;
        float v = 0.f;
        if (t >= 0 && t < TT) v = (x[((size_t)b*CINC + c)*TT + t] - mn[c]) * isd[c];
        xs[c][u] = v;
    }

    unsigned long long a0 = pack2(0.f, 0.f);
    unsigned long long a1 = pack2(0.f, 0.f);

    for (int c = 0; c < CINC; c++) {
        __syncthreads();
        // stage w1 transposed: w1t[k][m] = w1[m][c][k]
        for (int i = tid; i < 64*64; i += 256) {
            int m = i >> 6, k = i & 63;
            w1t[k][m] = w1[((size_t)m*CINC + c)*ATOM + k];
        }
        __syncthreads();
        const float* xrow = xs[c] + li*32 + kbase;
        #pragma unroll 8
        for (int k = 0; k < 32; k++) {
            float xv = xrow[k];
            unsigned long long x2 = pack2(xv, xv);
            const unsigned long long* wrow =
                (const unsigned long long*)(&w1t[kbase + k][mq*4]);
            ffma2(a0, wrow[0], x2);
            ffma2(a1, wrow[1], x2);
        }
    }
    // write partials
    {
        float2 v0 = unpack2(a0), v1 = unpack2(a1);
        hp[half][4*mq+0][li] = v0.x;
        hp[half][4*mq+1][li] = v0.y;
        hp[half][4*mq+2][li] = v1.x;
        hp[half][4*mq+3][li] = v1.y;
    }
    __syncthreads();
    // combine halves + bias + relu
    for (int i = tid; i < 64*8; i += 256) {
        int m = i >> 3, l = i & 7;
        hs[m][l] = fmaxf(hp[0][m][l] + hp[1][m][l] + b1[m], 0.f);
    }
    __syncthreads();

    float sc = scale[0];
    #pragma unroll
    for (int j = 0; j < 4; j++) {
        int idx = tid + j*256;           // idx = a*8 + li
        int a = idx >> 3, lli = idx & 7;
        float z = 0.f;
        const float* w2r = w2 + (size_t)a*64;
        #pragma unroll 8
        for (int m = 0; m < 64; m++) z += hs[m][lli] * w2r[m];
        z = (z + b2[a]) * sc;
        g_zraw[((size_t)b*NAC + a)*LL + l0 + lli] = z;
    }
}

// ---------------- pool residual (compact) + l1 partials ----------------
__global__ void k_pool(int s, int first, int scaleIdx) {
    int Ls = LL / s;
    int Np = NB*NAC*Ls;
    float lsum = 0.f;
    for (int e = blockIdx.x*256 + threadIdx.x; e < Np; e += 512*256) {
        int j  = e % Ls;
        int ba = e / Ls;
        size_t base = (size_t)ba*LL + (size_t)j*s;
        float sum = 0.f;
        for (int q = 0; q < s; q++) {
            float v = g_zraw[base+q];
            if (!first) v -= g_R[base+q];
            sum += v;
        }
        float avg = sum / (float)s;
        g_zup[(size_t)ba*LL + j] = avg;
        lsum += fabsf(avg);
    }
    __shared__ float red[256];
    red[threadIdx.x] = lsum;
    __syncthreads();
    for (int o = 128; o > 0; o >>= 1) {
        if (threadIdx.x < o) red[threadIdx.x] += red[threadIdx.x+o];
        __syncthreads();
    }
    if (threadIdx.x == 0) g_part[scaleIdx*512 + blockIdx.x] = red[0];
}

// ---------------- folded shapelet conv: FFMA2 + register prefetch of next-ni W ----
// grid (16, NB): blockIdx.x = wtile*S + r. 256 threads, 8no(4 packs) x 2w tile.
template<int S, int TP>
__global__ void k_fconv(int first) {
    constexpr int ZW = TP + 32;      // Zs window per ni
    constexpr int ZR = TP + 33;      // Zs row stride
    constexpr int LS = LL / S;
    constexpr int N4  = TP*NAC/4;             // float4 elements of one ni's W slice
    constexpr int NPF = (N4 + 255) / 256;     // per-thread prefetch float4s
    const float* W = (S == 4) ? g_W4 : ((S == 2) ? g_W2 : g_W1);

    extern __shared__ float smem[];
    float* Zs = smem;                // [NAC][ZR]
    float* As = smem + NAC*ZR;       // [TP][NAC]

    int b  = blockIdx.y;
    int wt = blockIdx.x / S;
    int r  = blockIdx.x % S;
    int w0 = wt * 32;
    int q_r = -(((31 - r) + S - 1) / S);      // floor((r-31)/S)
    int ph  = (r - 31) - S*q_r;               // in [0, S)

    int tid = threadIdx.x;
    int tx = tid & 15, ty = tid >> 4;
    int no0 = ty * 8;
    int tbase = 2*tx;

    const float* zb = g_zup + (size_t)b*NAC*LL;
    for (int i = tid; i < NAC*ZW; i += 256) {
        int ni = i / ZW, jw = i - ni*ZW;
        int j = w0 + q_r + jw;
        Zs[ni*ZR + jw] = (j >= 0 && j < LS) ? zb[(size_t)ni*LL + j] : 0.f;
    }

    // preload ni = 0 W slice into registers
    float4 pf[NPF];
    {
        const float4* src = (const float4*)(W + ((size_t)(0*S + ph)*TP)*NAC);
        #pragma unroll
        for (int u = 0; u < NPF; u++) {
            int i = tid + u*256;
            if (i < N4) pf[u] = src[i];
        }
    }

    unsigned long long acc2[4][2];
    #pragma unroll
    for (int p = 0; p < 4; p++) { acc2[p][0] = pack2(0.f, 0.f); acc2[p][1] = pack2(0.f, 0.f); }

    for (int ni = 0; ni < NAC; ni++) {
        __syncthreads();                      // prior compute done (and Zs ready on ni=0)
        {
            float4* dst = (float4*)As;
            #pragma unroll
            for (int u = 0; u < NPF; u++) {
                int i = tid + u*256;
                if (i < N4) dst[i] = pf[u];
            }
        }
        __syncthreads();
        if (ni + 1 < NAC) {                   // prefetch next ni; latency hidden by compute
            const float4* src = (const float4*)(W + ((size_t)((ni+1)*S + ph)*TP)*NAC);
            #pragma unroll
            for (int u = 0; u < NPF; u++) {
                int i = tid + u*256;
                if (i < N4) pf[u] = src[i];
            }
        }
        const float* zrow = Zs + ni*ZR + tbase;
        #pragma unroll 4
        for (int jj = 0; jj < TP; jj++) {
            float z0s = zrow[jj];
            float z1s = zrow[jj+1];
            unsigned long long z0 = pack2(z0s, z0s);
            unsigned long long z1 = pack2(z1s, z1s);
            const unsigned long long* arow = (const unsigned long long*)(As + jj*NAC + no0);
            #pragma unroll
            for (int p = 0; p < 4; p++) {
                unsigned long long a2 = arow[p];
                ffma2(acc2[p][0], a2, z0);
                ffma2(acc2[p][1], a2, z1);
            }
        }
    }

    float* Rb = g_R + (size_t)b*NAC*LL;
    #pragma unroll
    for (int p = 0; p < 4; p++) {
        #pragma unroll
        for (int j = 0; j < 2; j++) {
            float2 v = unpack2(acc2[p][j]);
            int no = no0 + 2*p;
            int t  = S*(w0 + tbase + j) + r;
            if (first) {
                Rb[(size_t)no*LL + t]     = v.x;
                Rb[(size_t)(no+1)*LL + t] = v.y;
            } else {
                Rb[(size_t)no*LL + t]     += v.x;
                Rb[(size_t)(no+1)*LL + t] += v.y;
            }
        }
    }
}

// ---------------- decoder with folded weights + denorm ----------------
__global__ void k_dec(const float* __restrict__ dec_b, float* __restrict__ out) {
    __shared__ float Rs[NAC][19];
    int b  = blockIdx.y;
    int p0 = blockIdx.x * 16;
    int tid = threadIdx.x;
    int r = tid & 31, c = tid >> 5;

    const float* Rb = g_R + (size_t)b*NAC*LL;
    for (int i = tid; i < NAC*18; i += 384) {
        int na = i / 18, pp = i - na*18;
        int p = p0 - 1 + pp;
        Rs[na][pp] = (p >= 0 && p < LL) ? Rb[(size_t)na*LL + p] : 0.f;
    }
    __syncthreads();

    float acc[16];
    #pragma unroll
    for (int i = 0; i < 16; i++) acc[i] = 0.f;

    for (int na = 0; na < NAC; na++) {
        const float* wf = g_Wf + ((size_t)na*3)*CINC*32 + c*32 + r;
        float w0 = wf[0];
        float w1 = wf[CINC*32];
        float w2 = wf[2*CINC*32];
        #pragma unroll
        for (int pl = 0; pl < 16; pl++)
            acc[pl] += w0*Rs[na][pl] + w1*Rs[na][pl+1] + w2*Rs[na][pl+2];
    }

    float sd  = g_std [b*CINC + c];
    float mnv = g_mean[b*CINC + c];
    float db  = dec_b[c];
    #pragma unroll
    for (int pl = 0; pl < 16; pl++) {
        int p = p0 + pl;
        if (p < 511) {
            int t = p*32 + r;
            out[((size_t)b*CINC + c)*TT + t] = (acc[pl] + db)*sd + mnv;
        }
    }
}

// ---------------- finalize scalars (deterministic, fixed-order) ----------------
__global__ void k_final(float* __restrict__ out, int out_size) {
    if (blockIdx.x != 0 || threadIdx.x != 0) return;
    float tot = 0.f;
    const float cnt[3] = { (float)(NB*NAC*(LL/4)), (float)(NB*NAC*(LL/2)), (float)(NB*NAC*LL) };
    for (int sIdx = 0; sIdx < 3; sIdx++) {
        float ssum = 0.f;
        for (int i = 0; i < 512; i++) ssum += g_part[sIdx*512 + i];
        tot += ssum / cnt[sIdx];
    }
    if (out_size > NOUT)     out[NOUT]     = 0.f;
    if (out_size > NOUT + 1) out[NOUT + 1] = tot * 0.01f;
}

// ---------------- launch ----------------
extern "C" void kernel_launch(void* const* d_in, const int* in_sizes, int n_in,
                              void* d_out, int out_size) {
    const float* x        = (const float*)d_in[0];
    const float* stem_w1  = (const float*)d_in[1];
    const float* stem_b1  = (const float*)d_in[2];
    const float* stem_w2  = (const float*)d_in[3];
    const float* stem_b2  = (const float*)d_in[4];
    const float* stem_sc  = (const float*)d_in[5];
    const float* shapelet = (const float*)d_in[6];
    const float* dec_w    = (const float*)d_in[7];
    const float* dec_b    = (const float*)d_in[8];
    float* out = (float*)d_out;

    const int SM4 = (NAC*(17+33) + 17*NAC) * (int)sizeof(float);
    const int SM2 = (NAC*(33+33) + 33*NAC) * (int)sizeof(float);
    const int SM1 = (NAC*(64+33) + 64*NAC) * (int)sizeof(float);
    cudaFuncSetAttribute(k_fconv<4,17>, cudaFuncAttributeMaxDynamicSharedMemorySize, SM4);
    cudaFuncSetAttribute(k_fconv<2,33>, cudaFuncAttributeMaxDynamicSharedMemorySize, SM2);
    cudaFuncSetAttribute(k_fconv<1,64>, cudaFuncAttributeMaxDynamicSharedMemorySize, SM1);

    k_meanstd<<<NB*CINC, 256>>>(x);
    k_prep<<<NAC, 256>>>(shapelet);
    k_fold<<<(NAC*3*CINC*32 + 255)/256, 256>>>(dec_w);
    k_stem<<<dim3(64, NB), 256>>>(x, stem_w1, stem_b1, stem_w2, stem_b2, stem_sc);

    // scale 4 (first: residual = z_raw, R = rec)
    k_pool<<<512, 256>>>(4, 1, 0);
    k_fconv<4,17><<<dim3(16, NB), 256, SM4>>>(1);
    // scale 2
    k_pool<<<512, 256>>>(2, 0, 1);
    k_fconv<2,33><<<dim3(16, NB), 256, SM2>>>(0);
    // scale 1
    k_pool<<<512, 256>>>(1, 0, 2);
    k_fconv<1,64><<<dim3(16, NB), 256, SM1>>>(0);

    k_dec<<<dim3(32, NB), 384>>>(dec_b, out);
    k_final<<<1, 32>>>(out, out_size);
}

// round 10
// speedup vs baseline: 1.6987x; 1.0129x over previous
#include <cuda_runtime.h>
#include <math.h>

#define NB   16
#define CINC 12
#define TT   16352
#define ATOM 64
#define NAC  128
#define LL   512
#define NOUT (NB*CINC*TT)
#define SL   16   // l positions per stem block

// ---------------- device scratch (no allocations allowed) ----------------
__device__ float g_mean[NB*CINC];
__device__ float g_std [NB*CINC];
__device__ float g_zraw[NB*NAC*LL];
__device__ float g_zup [NB*NAC*LL];
__device__ float g_R   [NB*NAC*LL];
__device__ float g_W1  [NAC*1*64*NAC];  // folded weights S=1: [ni][jj][no]
__device__ float g_W2  [NAC*2*33*NAC];  // folded weights S=2: [ni][ph][jj][no]
__device__ float g_W4  [NAC*4*17*NAC];  // folded weights S=4: [ni][ph][jj][no]
__device__ float g_Wf  [NAC*3*CINC*32]; // folded decoder weights
__device__ float g_part[3*512];

// ---------------- packed f32x2 helpers ----------------
__device__ __forceinline__ void ffma2(unsigned long long &d, unsigned long long a, unsigned long long b) {
    asm("fma.rn.f32x2 %0, %1, %2, %0;" : "+l"(d) : "l"(a), "l"(b));
}
__device__ __forceinline__ unsigned long long pack2(float lo, float hi) {
    unsigned long long r;
    asm("mov.b64 %0, {%1, %2};" : "=l"(r) : "f"(lo), "f"(hi));
    return r;
}
__device__ __forceinline__ float2 unpack2(unsigned long long v) {
    float2 r;
    asm("mov.b64 {%0, %1}, %2;" : "=f"(r.x), "=f"(r.y) : "l"(v));
    return r;
}

// ---------------- mean / std per (b,c) ----------------
__global__ void k_meanstd(const float* __restrict__ x) {
    int row = blockIdx.x;
    const float* xr = x + (size_t)row * TT;
    float s = 0.f, s2 = 0.f;
    for (int t = threadIdx.x; t < TT; t += 256) {
        float v = xr[t]; s += v; s2 += v*v;
    }
    __shared__ float ss[256], sq[256];
    ss[threadIdx.x] = s; sq[threadIdx.x] = s2;
    __syncthreads();
    for (int o = 128; o > 0; o >>= 1) {
        if (threadIdx.x < o) { ss[threadIdx.x] += ss[threadIdx.x+o]; sq[threadIdx.x] += sq[threadIdx.x+o]; }
        __syncthreads();
    }
    if (threadIdx.x == 0) {
        float m  = ss[0] / (float)TT;
        float var = sq[0] / (float)TT - m*m;
        g_mean[row] = m;
        g_std[row]  = sqrtf(var + 1e-5f);
    }
}

// ---------------- prep: normalize shapelets + build folded transposed weights ----
__global__ void k_prep(const float* __restrict__ shapelets) {
    __shared__ float raw[NAC][ATOM + 1];
    __shared__ float inv[NAC];
    int ni = blockIdx.x;
    int tid = threadIdx.x;

    for (int i = tid; i < NAC*ATOM; i += 256) {
        int no = i >> 6, k = i & 63;
        raw[no][k] = shapelets[((size_t)no*NAC + ni)*ATOM + k];
    }
    __syncthreads();
    if (tid < NAC) {
        float ssum = 0.f;
        #pragma unroll 8
        for (int k = 0; k < ATOM; k++) { float v = raw[tid][k]; ssum += v*v; }
        inv[tid] = 1.f / fmaxf(sqrtf(ssum), 1e-8f);
    }
    __syncthreads();

    for (int i = tid; i < 64*NAC; i += 256) {
        int no = i & 127, jj = i >> 7;
        g_W1[((size_t)ni*64 + jj)*NAC + no] = raw[no][jj] * inv[no];
    }
    for (int i = tid; i < 2*33*NAC; i += 256) {
        int no = i & 127;
        int rest = i >> 7;
        int jj = rest % 33, ph = rest / 33;
        int k0 = 2*jj - ph, k1 = k0 + 1;
        if (k0 < 0)  k0 = 0;
        if (k1 > 63) k1 = 63;
        float acc = 0.f;
        for (int k = k0; k <= k1; k++) acc += raw[no][k];
        g_W2[((size_t)(ni*2 + ph)*33 + jj)*NAC + no] = acc * inv[no];
    }
    for (int i = tid; i < 4*17*NAC; i += 256) {
        int no = i & 127;
        int rest = i >> 7;
        int jj = rest % 17, ph = rest / 17;
        int k0 = 4*jj - ph, k1 = k0 + 3;
        if (k0 < 0)  k0 = 0;
        if (k1 > 63) k1 = 63;
        float acc = 0.f;
        for (int k = k0; k <= k1; k++) acc += raw[no][k];
        g_W4[((size_t)(ni*4 + ph)*17 + jj)*NAC + no] = acc * inv[no];
    }
}

// ---------------- fold decoder weights: Wf[na][d][c][r] ----------------
__global__ void k_fold(const float* __restrict__ dec_w) {
    int id = blockIdx.x*256 + threadIdx.x;
    if (id >= NAC*3*CINC*32) return;
    int r  = id & 31;
    int c  = (id >> 5) % CINC;
    int dd = (id / (32*CINC)) % 3;
    int na = id / (32*CINC*3);
    int k0, k1;
    if (dd == 0)      { k0 = 0;      k1 = 30 - r; }
    else if (dd == 1) { k0 = 31 - r; k1 = 62 - r; }
    else              { k0 = 63 - r; k1 = 63;     }
    float acc = 0.f;
    const float* w = dec_w + ((size_t)c*NAC + na)*ATOM;
    for (int k = k0; k <= k1; k++) acc += w[k];
    g_Wf[((na*3 + dd)*CINC + c)*32 + r] = acc;
}

// ---------------- fused stem (FMA-bound layout) ----------------
// grid (32, NB), 256 threads. Block: 16 l x 64 m.
// Thread = (kq 0..3: k in [16kq,16kq+16), lp 0..7: l in {2lp,2lp+1}, mo 0..7:
// m-pairs {2mo+16p, +1} for p 0..3). x duplicated float2 + swizzle pad;
// w1t[k][m] row stride 66 via register transpose. Partials hp[kq] reduced in smem.
__global__ void k_stem(const float* __restrict__ x,
                       const float* __restrict__ w1, const float* __restrict__ b1,
                       const float* __restrict__ w2, const float* __restrict__ b2,
                       const float* __restrict__ scale) {
    extern __shared__ float sm[];
    float* xsdf = sm;                     // 12 * 594 float2 = 14256 floats
    float* w1t  = sm + CINC*594*2;        // 64*66 = 4224 floats
    float* hp   = w1t + 64*66;            // 4*64*16 = 4096 floats
    float* hs   = hp + 4*64*SL;           // 64*16 = 1024 floats
    __shared__ float mn[CINC], isd[CINC];

    int b  = blockIdx.y;
    int l0 = blockIdx.x * SL;
    int tid = threadIdx.x;
    int kq = tid >> 6;
    int lp = (tid >> 3) & 7;
    int mo = tid & 7;

    if (tid < CINC) { mn[tid] = g_mean[b*CINC+tid]; isd[tid] = 1.f / g_std[b*CINC+tid]; }
    __syncthreads();

    // stage x: duplicated pairs, swizzled index u -> u + (u>>5)
    int t0 = 32*l0 - 32;
    for (int i = tid; i < CINC*544; i += 256) {
        int c = i / 544, u = i - c*544;
        int t = t0 + u;
        float v = 0.f;
        if (t >= 0 && t < TT) v = (x[((size_t)b*CINC + c)*TT + t] - mn[c]) * isd[c];
        int us = u + (u >> 5);
        float2* dst = (float2*)(xsdf + (c*594 + us)*2);
        *dst = make_float2(v, v);
    }

    unsigned long long acc[4][2];
    #pragma unroll
    for (int p = 0; p < 4; p++) { acc[p][0] = pack2(0.f, 0.f); acc[p][1] = pack2(0.f, 0.f); }

    for (int c = 0; c < CINC; c++) {
        __syncthreads();
        // stage w1t[k][m] via register transpose: coalesced LDG.128, STS rows
        {
            int k4 = (tid & 15) * 4;
            int mBase = tid >> 4;          // 0..15
            #pragma unroll
            for (int pass = 0; pass < 4; pass++) {
                int m = pass*16 + mBase;
                const float4 wv = *(const float4*)(w1 + ((size_t)m*CINC + c)*ATOM + k4);
                w1t[(k4+0)*66 + m] = wv.x;
                w1t[(k4+1)*66 + m] = wv.y;
                w1t[(k4+2)*66 + m] = wv.z;
                w1t[(k4+3)*66 + m] = wv.w;
            }
        }
        __syncthreads();
        const unsigned long long* xc2 = (const unsigned long long*)(xsdf + c*594*2);
        #pragma unroll 4
        for (int kk = 0; kk < 16; kk++) {
            int k  = 16*kq + kk;
            int u0 = 64*lp + k;
            int u1 = u0 + 32;
            unsigned long long x0 = xc2[u0 + (u0 >> 5)];
            unsigned long long x1 = xc2[u1 + (u1 >> 5)];
            const unsigned long long* wr = (const unsigned long long*)(w1t + k*66);
            #pragma unroll
            for (int p = 0; p < 4; p++) {
                unsigned long long wv = wr[mo + 8*p];   // floats m=2mo+16p, m+1
                ffma2(acc[p][0], wv, x0);
                ffma2(acc[p][1], wv, x1);
            }
        }
    }

    // write k-quarter partials
    #pragma unroll
    for (int p = 0; p < 4; p++) {
        int m = 2*mo + 16*p;
        #pragma unroll
        for (int j = 0; j < 2; j++) {
            float2 v = unpack2(acc[p][j]);
            int l = 2*lp + j;
            hp[(kq*64 + m)*SL + l]       = v.x;
            hp[(kq*64 + m + 1)*SL + l]   = v.y;
        }
    }
    __syncthreads();
    // reduce quarters + bias + relu
    for (int i = tid; i < 64*SL; i += 256) {
        int m = i >> 4, l = i & 15;
        float s = hp[(0*64+m)*SL + l] + hp[(1*64+m)*SL + l]
                + hp[(2*64+m)*SL + l] + hp[(3*64+m)*SL + l];
        hs[m*SL + l] = fmaxf(s + b1[m], 0.f);
    }
    __syncthreads();

    // 1x1 conv + scale
    float sc = scale[0];
    #pragma unroll
    for (int j = 0; j < 8; j++) {
        int idx = tid + j*256;        // a*16 + l
        int a = idx >> 4, l = idx & 15;
        float z = 0.f;
        const float* w2r = w2 + (size_t)a*64;
        #pragma unroll 8
        for (int m = 0; m < 64; m++) z += hs[m*SL + l] * w2r[m];
        z = (z + b2[a]) * sc;
        g_zraw[((size_t)b*NAC + a)*LL + l0 + l] = z;
    }
}

// ---------------- pool residual (compact) + l1 partials ----------------
__global__ void k_pool(int s, int first, int scaleIdx) {
    int Ls = LL / s;
    int Np = NB*NAC*Ls;
    float lsum = 0.f;
    for (int e = blockIdx.x*256 + threadIdx.x; e < Np; e += 512*256) {
        int j  = e % Ls;
        int ba = e / Ls;
        size_t base = (size_t)ba*LL + (size_t)j*s;
        float sum = 0.f;
        for (int q = 0; q < s; q++) {
            float v = g_zraw[base+q];
            if (!first) v -= g_R[base+q];
            sum += v;
        }
        float avg = sum / (float)s;
        g_zup[(size_t)ba*LL + j] = avg;
        lsum += fabsf(avg);
    }
    __shared__ float red[256];
    red[threadIdx.x] = lsum;
    __syncthreads();
    for (int o = 128; o > 0; o >>= 1) {
        if (threadIdx.x < o) red[threadIdx.x] += red[threadIdx.x+o];
        __syncthreads();
    }
    if (threadIdx.x == 0) g_part[scaleIdx*512 + blockIdx.x] = red[0];
}

// ---------------- folded shapelet conv: FFMA2 + W prefetch + z-carry ----------------
template<int S, int TP>
__global__ void k_fconv(int first) {
    constexpr int ZW = TP + 32;
    constexpr int ZR = TP + 33;
    constexpr int LS = LL / S;
    constexpr int N4  = TP*NAC/4;
    constexpr int NPF = (N4 + 255) / 256;
    const float* W = (S == 4) ? g_W4 : ((S == 2) ? g_W2 : g_W1);

    extern __shared__ float smem[];
    float* Zs = smem;                // [NAC][ZR]
    float* As = smem + NAC*ZR;       // [TP][NAC]

    int b  = blockIdx.y;
    int wt = blockIdx.x / S;
    int r  = blockIdx.x % S;
    int w0 = wt * 32;
    int q_r = -(((31 - r) + S - 1) / S);
    int ph  = (r - 31) - S*q_r;

    int tid = threadIdx.x;
    int tx = tid & 15, ty = tid >> 4;
    int no0 = ty * 8;
    int tbase = 2*tx;

    const float* zb = g_zup + (size_t)b*NAC*LL;
    for (int i = tid; i < NAC*ZW; i += 256) {
        int ni = i / ZW, jw = i - ni*ZW;
        int j = w0 + q_r + jw;
        Zs[ni*ZR + jw] = (j >= 0 && j < LS) ? zb[(size_t)ni*LL + j] : 0.f;
    }

    float4 pf[NPF];
    {
        const float4* src = (const float4*)(W + ((size_t)(0*S + ph)*TP)*NAC);
        #pragma unroll
        for (int u = 0; u < NPF; u++) {
            int i = tid + u*256;
            if (i < N4) pf[u] = src[i];
        }
    }

    unsigned long long acc2[4][2];
    #pragma unroll
    for (int p = 0; p < 4; p++) { acc2[p][0] = pack2(0.f, 0.f); acc2[p][1] = pack2(0.f, 0.f); }

    for (int ni = 0; ni < NAC; ni++) {
        __syncthreads();
        {
            float4* dst = (float4*)As;
            #pragma unroll
            for (int u = 0; u < NPF; u++) {
                int i = tid + u*256;
                if (i < N4) dst[i] = pf[u];
            }
        }
        __syncthreads();
        if (ni + 1 < NAC) {
            const float4* src = (const float4*)(W + ((size_t)((ni+1)*S + ph)*TP)*NAC);
            #pragma unroll
            for (int u = 0; u < NPF; u++) {
                int i = tid + u*256;
                if (i < N4) pf[u] = src[i];
            }
        }
        const float* zrow = Zs + ni*ZR + tbase;
        float zc = zrow[0];
        unsigned long long zc2 = pack2(zc, zc);
        #pragma unroll 4
        for (int jj = 0; jj < TP; jj++) {
            unsigned long long z0 = zc2;          // carried: = zrow[jj] dup
            float z1s = zrow[jj+1];
            unsigned long long z1 = pack2(z1s, z1s);
            zc2 = z1;
            const unsigned long long* arow = (const unsigned long long*)(As + jj*NAC + no0);
            #pragma unroll
            for (int p = 0; p < 4; p++) {
                unsigned long long a2 = arow[p];
                ffma2(acc2[p][0], a2, z0);
                ffma2(acc2[p][1], a2, z1);
            }
        }
    }

    float* Rb = g_R + (size_t)b*NAC*LL;
    #pragma unroll
    for (int p = 0; p < 4; p++) {
        #pragma unroll
        for (int j = 0; j < 2; j++) {
            float2 v = unpack2(acc2[p][j]);
            int no = no0 + 2*p;
            int t  = S*(w0 + tbase + j) + r;
            if (first) {
                Rb[(size_t)no*LL + t]     = v.x;
                Rb[(size_t)(no+1)*LL + t] = v.y;
            } else {
                Rb[(size_t)no*LL + t]     += v.x;
                Rb[(size_t)(no+1)*LL + t] += v.y;
            }
        }
    }
}

// ---------------- decoder with folded weights + denorm ----------------
__global__ void k_dec(const float* __restrict__ dec_b, float* __restrict__ out) {
    __shared__ float Rs[NAC][19];
    int b  = blockIdx.y;
    int p0 = blockIdx.x * 16;
    int tid = threadIdx.x;
    int r = tid & 31, c = tid >> 5;

    const float* Rb = g_R + (size_t)b*NAC*LL;
    for (int i = tid; i < NAC*18; i += 384) {
        int na = i / 18, pp = i - na*18;
        int p = p0 - 1 + pp;
        Rs[na][pp] = (p >= 0 && p < LL) ? Rb[(size_t)na*LL + p] : 0.f;
    }
    __syncthreads();

    float acc[16];
    #pragma unroll
    for (int i = 0; i < 16; i++) acc[i] = 0.f;

    for (int na = 0; na < NAC; na++) {
        const float* wf = g_Wf + ((size_t)na*3)*CINC*32 + c*32 + r;
        float w0 = wf[0];
        float w1 = wf[CINC*32];
        float w2 = wf[2*CINC*32];
        #pragma unroll
        for (int pl = 0; pl < 16; pl++)
            acc[pl] += w0*Rs[na][pl] + w1*Rs[na][pl+1] + w2*Rs[na][pl+2];
    }

    float sd  = g_std [b*CINC + c];
    float mnv = g_mean[b*CINC + c];
    float db  = dec_b[c];
    #pragma unroll
    for (int pl = 0; pl < 16; pl++) {
        int p = p0 + pl;
        if (p < 511) {
            int t = p*32 + r;
            out[((size_t)b*CINC + c)*TT + t] = (acc[pl] + db)*sd + mnv;
        }
    }
}

// ---------------- finalize scalars ----------------
__global__ void k_final(float* __restrict__ out, int out_size) {
    if (blockIdx.x != 0 || threadIdx.x != 0) return;
    float tot = 0.f;
    const float cnt[3] = { (float)(NB*NAC*(LL/4)), (float)(NB*NAC*(LL/2)), (float)(NB*NAC*LL) };
    for (int sIdx = 0; sIdx < 3; sIdx++) {
        float ssum = 0.f;
        for (int i = 0; i < 512; i++) ssum += g_part[sIdx*512 + i];
        tot += ssum / cnt[sIdx];
    }
    if (out_size > NOUT)     out[NOUT]     = 0.f;
    if (out_size > NOUT + 1) out[NOUT + 1] = tot * 0.01f;
}

// ---------------- launch ----------------
extern "C" void kernel_launch(void* const* d_in, const int* in_sizes, int n_in,
                              void* d_out, int out_size) {
    const float* x        = (const float*)d_in[0];
    const float* stem_w1  = (const float*)d_in[1];
    const float* stem_b1  = (const float*)d_in[2];
    const float* stem_w2  = (const float*)d_in[3];
    const float* stem_b2  = (const float*)d_in[4];
    const float* stem_sc  = (const float*)d_in[5];
    const float* shapelet = (const float*)d_in[6];
    const float* dec_w    = (const float*)d_in[7];
    const float* dec_b    = (const float*)d_in[8];
    float* out = (float*)d_out;

    const int SM4 = (NAC*(17+33) + 17*NAC) * (int)sizeof(float);
    const int SM2 = (NAC*(33+33) + 33*NAC) * (int)sizeof(float);
    const int SM1 = (NAC*(64+33) + 64*NAC) * (int)sizeof(float);
    const int SMEM_STEM = (CINC*594*2 + 64*66 + 4*64*SL + 64*SL) * (int)sizeof(float); // 94400 B
    cudaFuncSetAttribute(k_fconv<4,17>, cudaFuncAttributeMaxDynamicSharedMemorySize, SM4);
    cudaFuncSetAttribute(k_fconv<2,33>, cudaFuncAttributeMaxDynamicSharedMemorySize, SM2);
    cudaFuncSetAttribute(k_fconv<1,64>, cudaFuncAttributeMaxDynamicSharedMemorySize, SM1);
    cudaFuncSetAttribute(k_stem, cudaFuncAttributeMaxDynamicSharedMemorySize, SMEM_STEM);

    k_meanstd<<<NB*CINC, 256>>>(x);
    k_prep<<<NAC, 256>>>(shapelet);
    k_fold<<<(NAC*3*CINC*32 + 255)/256, 256>>>(dec_w);
    k_stem<<<dim3(LL/SL, NB), 256, SMEM_STEM>>>(x, stem_w1, stem_b1, stem_w2, stem_b2, stem_sc);

    // scale 4 (first: residual = z_raw, R = rec)
    k_pool<<<512, 256>>>(4, 1, 0);
    k_fconv<4,17><<<dim3(16, NB), 256, SM4>>>(1);
    // scale 2
    k_pool<<<512, 256>>>(2, 0, 1);
    k_fconv<2,33><<<dim3(16, NB), 256, SM2>>>(0);
    // scale 1
    k_pool<<<512, 256>>>(1, 0, 2);
    k_fconv<1,64><<<dim3(16, NB), 256, SM1>>>(0);

    k_dec<<<dim3(32, NB), 384>>>(dec_b, out);
    k_final<<<1, 32>>>(out, out_size);
}

// round 11
// speedup vs baseline: 1.9493x; 1.1475x over previous
#include <cuda_runtime.h>
#include <math.h>

#define NB   16
#define CINC 12
#define TT   16352
#define ATOM 64
#define NAC  128
#define LL   512
#define NOUT (NB*CINC*TT)
#define SL   16   // l positions per stem block

typedef unsigned long long ull;

// ---------------- device scratch (no allocations allowed) ----------------
__device__ float g_mean[NB*CINC];
__device__ float g_std [NB*CINC];
__device__ float g_zraw[NB*NAC*LL];
__device__ float g_zup [NB*NAC*LL];
__device__ float g_R   [NB*NAC*LL];
__device__ float g_W1  [NAC*1*64*NAC];  // folded weights S=1: [ni][jj][no]
__device__ float g_W2  [NAC*2*33*NAC];  // folded weights S=2: [ni][ph][jj][no]
__device__ float g_W4  [NAC*4*17*NAC];  // folded weights S=4: [ni][ph][jj][no]
__device__ float g_w1t [CINC*64*64];    // stem w1 transposed: [c][k][m]
__device__ float g_Wf  [NAC*3*CINC*32]; // folded decoder weights
__device__ float g_part[3*512];

// ---------------- packed f32x2 helpers ----------------
__device__ __forceinline__ void ffma2(ull &d, ull a, ull b) {
    asm("fma.rn.f32x2 %0, %1, %2, %0;" : "+l"(d) : "l"(a), "l"(b));
}
__device__ __forceinline__ ull pack2(float lo, float hi) {
    ull r;
    asm("mov.b64 %0, {%1, %2};" : "=l"(r) : "f"(lo), "f"(hi));
    return r;
}
__device__ __forceinline__ float2 unpack2(ull v) {
    float2 r;
    asm("mov.b64 {%0, %1}, %2;" : "=f"(r.x), "=f"(r.y) : "l"(v));
    return r;
}

// ---------------- mean / std per (b,c) ----------------
__global__ void k_meanstd(const float* __restrict__ x) {
    int row = blockIdx.x;
    const float* xr = x + (size_t)row * TT;
    float s = 0.f, s2 = 0.f;
    for (int t = threadIdx.x; t < TT; t += 256) {
        float v = xr[t]; s += v; s2 += v*v;
    }
    __shared__ float ss[256], sq[256];
    ss[threadIdx.x] = s; sq[threadIdx.x] = s2;
    __syncthreads();
    for (int o = 128; o > 0; o >>= 1) {
        if (threadIdx.x < o) { ss[threadIdx.x] += ss[threadIdx.x+o]; sq[threadIdx.x] += sq[threadIdx.x+o]; }
        __syncthreads();
    }
    if (threadIdx.x == 0) {
        float m  = ss[0] / (float)TT;
        float var = sq[0] / (float)TT - m*m;
        g_mean[row] = m;
        g_std[row]  = sqrtf(var + 1e-5f);
    }
}

// ---------------- prep: normalize shapelets + build folded transposed weights ----
__global__ void k_prep(const float* __restrict__ shapelets) {
    __shared__ float raw[NAC][ATOM + 1];
    __shared__ float inv[NAC];
    int ni = blockIdx.x;
    int tid = threadIdx.x;

    for (int i = tid; i < NAC*ATOM; i += 256) {
        int no = i >> 6, k = i & 63;
        raw[no][k] = shapelets[((size_t)no*NAC + ni)*ATOM + k];
    }
    __syncthreads();
    if (tid < NAC) {
        float ssum = 0.f;
        #pragma unroll 8
        for (int k = 0; k < ATOM; k++) { float v = raw[tid][k]; ssum += v*v; }
        inv[tid] = 1.f / fmaxf(sqrtf(ssum), 1e-8f);
    }
    __syncthreads();

    for (int i = tid; i < 64*NAC; i += 256) {
        int no = i & 127, jj = i >> 7;
        g_W1[((size_t)ni*64 + jj)*NAC + no] = raw[no][jj] * inv[no];
    }
    for (int i = tid; i < 2*33*NAC; i += 256) {
        int no = i & 127;
        int rest = i >> 7;
        int jj = rest % 33, ph = rest / 33;
        int k0 = 2*jj - ph, k1 = k0 + 1;
        if (k0 < 0)  k0 = 0;
        if (k1 > 63) k1 = 63;
        float acc = 0.f;
        for (int k = k0; k <= k1; k++) acc += raw[no][k];
        g_W2[((size_t)(ni*2 + ph)*33 + jj)*NAC + no] = acc * inv[no];
    }
    for (int i = tid; i < 4*17*NAC; i += 256) {
        int no = i & 127;
        int rest = i >> 7;
        int jj = rest % 17, ph = rest / 17;
        int k0 = 4*jj - ph, k1 = k0 + 3;
        if (k0 < 0)  k0 = 0;
        if (k1 > 63) k1 = 63;
        float acc = 0.f;
        for (int k = k0; k <= k1; k++) acc += raw[no][k];
        g_W4[((size_t)(ni*4 + ph)*17 + jj)*NAC + no] = acc * inv[no];
    }
}

// ---------------- stem w1 transpose: g_w1t[(c*64 + k)*64 + m] = w1[m][c][k] ----
__global__ void k_wstem(const float* __restrict__ w1) {
    int id = blockIdx.x*256 + threadIdx.x;
    if (id >= CINC*64*64) return;
    int m = id & 63;
    int k = (id >> 6) & 63;
    int c = id >> 12;
    g_w1t[id] = w1[((size_t)m*CINC + c)*ATOM + k];
}

// ---------------- fold decoder weights: Wf[na][d][c][r] ----------------
__global__ void k_fold(const float* __restrict__ dec_w) {
    int id = blockIdx.x*256 + threadIdx.x;
    if (id >= NAC*3*CINC*32) return;
    int r  = id & 31;
    int c  = (id >> 5) % CINC;
    int dd = (id / (32*CINC)) % 3;
    int na = id / (32*CINC*3);
    int k0, k1;
    if (dd == 0)      { k0 = 0;      k1 = 30 - r; }
    else if (dd == 1) { k0 = 31 - r; k1 = 62 - r; }
    else              { k0 = 63 - r; k1 = 63;     }
    float acc = 0.f;
    const float* w = dec_w + ((size_t)c*NAC + na)*ATOM;
    for (int k = k0; k <= k1; k++) acc += w[k];
    g_Wf[((na*3 + dd)*CINC + c)*32 + r] = acc;
}

// ---------------- fused stem (FMA-bound layout + w prefetch) ----------------
// grid (32, NB), 256 threads. Block: 16 l x 64 m. w1 staged from g_w1t (no
// in-kernel transpose), next-c slice register-prefetched during compute.
__global__ void k_stem(const float* __restrict__ x,
                       const float* __restrict__ b1,
                       const float* __restrict__ w2, const float* __restrict__ b2,
                       const float* __restrict__ scale) {
    extern __shared__ float sm[];
    float* xsdf = sm;                     // 12 * 594 float2 = 14256 floats
    float* w1t  = sm + CINC*594*2;        // 64*68 = 4352 floats
    float* hp   = w1t + 64*68;            // 4*64*16 = 4096 floats
    float* hs   = hp + 4*64*SL;           // 64*16 = 1024 floats
    __shared__ float mn[CINC], isd[CINC];

    int b  = blockIdx.y;
    int l0 = blockIdx.x * SL;
    int tid = threadIdx.x;
    int kq = tid >> 6;
    int lp = (tid >> 3) & 7;
    int mo = tid & 7;

    if (tid < CINC) { mn[tid] = g_mean[b*CINC+tid]; isd[tid] = 1.f / g_std[b*CINC+tid]; }
    __syncthreads();

    // stage x: duplicated pairs, swizzled index u -> u + (u>>5)
    int t0 = 32*l0 - 32;
    for (int i = tid; i < CINC*544; i += 256) {
        int c = i / 544, u = i - c*544;
        int t = t0 + u;
        float v = 0.f;
        if (t >= 0 && t < TT) v = (x[((size_t)b*CINC + c)*TT + t] - mn[c]) * isd[c];
        int us = u + (u >> 5);
        float2* dst = (float2*)(xsdf + (c*594 + us)*2);
        *dst = make_float2(v, v);
    }

    // prefetch c = 0 w1 slice (4096 floats = 1024 float4)
    float4 pf[4];
    #pragma unroll
    for (int u = 0; u < 4; u++) pf[u] = ((const float4*)g_w1t)[tid + u*256];

    ull acc[4][2];
    #pragma unroll
    for (int p = 0; p < 4; p++) { acc[p][0] = pack2(0.f, 0.f); acc[p][1] = pack2(0.f, 0.f); }

    for (int c = 0; c < CINC; c++) {
        __syncthreads();
        // STS prefetched slice into w1t[k][m], row stride 68 (16B-aligned rows)
        #pragma unroll
        for (int u = 0; u < 4; u++) {
            int i = tid + u*256;
            int k = i >> 4, m4 = (i & 15) * 4;
            *(float4*)(w1t + k*68 + m4) = pf[u];
        }
        __syncthreads();
        if (c + 1 < CINC) {
            const float4* src = (const float4*)(g_w1t + (c+1)*4096);
            #pragma unroll
            for (int u = 0; u < 4; u++) pf[u] = src[tid + u*256];
        }
        const ull* xc2 = (const ull*)(xsdf + c*594*2);
        #pragma unroll 4
        for (int kk = 0; kk < 16; kk++) {
            int k  = 16*kq + kk;
            int u0 = 64*lp + k;
            int u1 = u0 + 32;
            ull x0 = xc2[u0 + (u0 >> 5)];
            ull x1 = xc2[u1 + (u1 >> 5)];
            const ull* wr = (const ull*)(w1t + k*68);
            #pragma unroll
            for (int p = 0; p < 4; p++) {
                ull wv = wr[mo + 8*p];   // floats m=2mo+16p, m+1
                ffma2(acc[p][0], wv, x0);
                ffma2(acc[p][1], wv, x1);
            }
        }
    }

    // write k-quarter partials
    #pragma unroll
    for (int p = 0; p < 4; p++) {
        int m = 2*mo + 16*p;
        #pragma unroll
        for (int j = 0; j < 2; j++) {
            float2 v = unpack2(acc[p][j]);
            int l = 2*lp + j;
            hp[(kq*64 + m)*SL + l]       = v.x;
            hp[(kq*64 + m + 1)*SL + l]   = v.y;
        }
    }
    __syncthreads();
    // reduce quarters + bias + relu
    for (int i = tid; i < 64*SL; i += 256) {
        int m = i >> 4, l = i & 15;
        float s = hp[(0*64+m)*SL + l] + hp[(1*64+m)*SL + l]
                + hp[(2*64+m)*SL + l] + hp[(3*64+m)*SL + l];
        hs[m*SL + l] = fmaxf(s + b1[m], 0.f);
    }
    __syncthreads();

    // 1x1 conv + scale
    float sc = scale[0];
    #pragma unroll
    for (int j = 0; j < 8; j++) {
        int idx = tid + j*256;        // a*16 + l
        int a = idx >> 4, l = idx & 15;
        float z = 0.f;
        const float* w2r = w2 + (size_t)a*64;
        #pragma unroll 8
        for (int m = 0; m < 64; m++) z += hs[m*SL + l] * w2r[m];
        z = (z + b2[a]) * sc;
        g_zraw[((size_t)b*NAC + a)*LL + l0 + l] = z;
    }
}

// ---------------- pool residual (compact) + l1 partials ----------------
__global__ void k_pool(int s, int first, int scaleIdx) {
    int Ls = LL / s;
    int Np = NB*NAC*Ls;
    float lsum = 0.f;
    for (int e = blockIdx.x*256 + threadIdx.x; e < Np; e += 512*256) {
        int j  = e % Ls;
        int ba = e / Ls;
        size_t base = (size_t)ba*LL + (size_t)j*s;
        float sum = 0.f;
        for (int q = 0; q < s; q++) {
            float v = g_zraw[base+q];
            if (!first) v -= g_R[base+q];
            sum += v;
        }
        float avg = sum / (float)s;
        g_zup[(size_t)ba*LL + j] = avg;
        lsum += fabsf(avg);
    }
    __shared__ float red[256];
    red[threadIdx.x] = lsum;
    __syncthreads();
    for (int o = 128; o > 0; o >>= 1) {
        if (threadIdx.x < o) red[threadIdx.x] += red[threadIdx.x+o];
        __syncthreads();
    }
    if (threadIdx.x == 0) g_part[scaleIdx*512 + blockIdx.x] = red[0];
}

// ---------------- folded shapelet conv: 8no x 4w FFMA2 tile + W prefetch ----
// grid (8, NB): blockIdx.x = wtile*S + r; 64-wide w tiles.
template<int S, int TP>
__global__ void __launch_bounds__(256, 1) k_fconv(int first) {
    constexpr int ZW = TP + 64;
    constexpr int ZR = TP + 65;
    constexpr int LS = LL / S;
    constexpr int N4  = TP*NAC/4;
    constexpr int NPF = (N4 + 255) / 256;
    const float* W = (S == 4) ? g_W4 : ((S == 2) ? g_W2 : g_W1);

    extern __shared__ float smem[];
    float* Zs = smem;                // [NAC][ZR]
    float* As = smem + NAC*ZR;       // [TP][NAC]

    int b  = blockIdx.y;
    int wt = blockIdx.x / S;
    int r  = blockIdx.x % S;
    int w0 = wt * 64;
    int q_r = -(((31 - r) + S - 1) / S);
    int ph  = (r - 31) - S*q_r;

    int tid = threadIdx.x;
    int tx = tid & 15, ty = tid >> 4;
    int no0 = ty * 8;
    int tbase = 4*tx;

    const float* zb = g_zup + (size_t)b*NAC*LL;
    for (int i = tid; i < NAC*ZW; i += 256) {
        int ni = i / ZW, jw = i - ni*ZW;
        int j = w0 + q_r + jw;
        Zs[ni*ZR + jw] = (j >= 0 && j < LS) ? zb[(size_t)ni*LL + j] : 0.f;
    }

    float4 pf[NPF];
    {
        const float4* src = (const float4*)(W + ((size_t)(0*S + ph)*TP)*NAC);
        #pragma unroll
        for (int u = 0; u < NPF; u++) {
            int i = tid + u*256;
            if (i < N4) pf[u] = src[i];
        }
    }

    ull acc2[4][4];
    #pragma unroll
    for (int p = 0; p < 4; p++)
        #pragma unroll
        for (int j = 0; j < 4; j++) acc2[p][j] = pack2(0.f, 0.f);

    for (int ni = 0; ni < NAC; ni++) {
        __syncthreads();
        {
            float4* dst = (float4*)As;
            #pragma unroll
            for (int u = 0; u < NPF; u++) {
                int i = tid + u*256;
                if (i < N4) dst[i] = pf[u];
            }
        }
        __syncthreads();
        if (ni + 1 < NAC) {
            const float4* src = (const float4*)(W + ((size_t)((ni+1)*S + ph)*TP)*NAC);
            #pragma unroll
            for (int u = 0; u < NPF; u++) {
                int i = tid + u*256;
                if (i < N4) pf[u] = src[i];
            }
        }
        const float* zrow = Zs + ni*ZR + tbase;
        ull q0 = pack2(zrow[0], zrow[0]);
        ull q1 = pack2(zrow[1], zrow[1]);
        ull q2 = pack2(zrow[2], zrow[2]);
        #pragma unroll 4
        for (int jj = 0; jj < TP; jj++) {
            float z3 = zrow[jj+3];
            ull q3 = pack2(z3, z3);
            const ull* arow = (const ull*)(As + jj*NAC + no0);
            #pragma unroll
            for (int p = 0; p < 4; p++) {
                ull a2 = arow[p];
                ffma2(acc2[p][0], a2, q0);
                ffma2(acc2[p][1], a2, q1);
                ffma2(acc2[p][2], a2, q2);
                ffma2(acc2[p][3], a2, q3);
            }
            q0 = q1; q1 = q2; q2 = q3;
        }
    }

    float* Rb = g_R + (size_t)b*NAC*LL;
    #pragma unroll
    for (int p = 0; p < 4; p++) {
        #pragma unroll
        for (int j = 0; j < 4; j++) {
            float2 v = unpack2(acc2[p][j]);
            int no = no0 + 2*p;
            int t  = S*(w0 + tbase + j) + r;
            if (first) {
                Rb[(size_t)no*LL + t]     = v.x;
                Rb[(size_t)(no+1)*LL + t] = v.y;
            } else {
                Rb[(size_t)no*LL + t]     += v.x;
                Rb[(size_t)(no+1)*LL + t] += v.y;
            }
        }
    }
}

// ---------------- decoder with folded weights + denorm ----------------
__global__ void k_dec(const float* __restrict__ dec_b, float* __restrict__ out) {
    __shared__ float Rs[NAC][19];
    int b  = blockIdx.y;
    int p0 = blockIdx.x * 16;
    int tid = threadIdx.x;
    int r = tid & 31, c = tid >> 5;

    const float* Rb = g_R + (size_t)b*NAC*LL;
    for (int i = tid; i < NAC*18; i += 384) {
        int na = i / 18, pp = i - na*18;
        int p = p0 - 1 + pp;
        Rs[na][pp] = (p >= 0 && p < LL) ? Rb[(size_t)na*LL + p] : 0.f;
    }
    __syncthreads();

    float acc[16];
    #pragma unroll
    for (int i = 0; i < 16; i++) acc[i] = 0.f;

    for (int na = 0; na < NAC; na++) {
        const float* wf = g_Wf + ((size_t)na*3)*CINC*32 + c*32 + r;
        float w0 = wf[0];
        float w1 = wf[CINC*32];
        float w2 = wf[2*CINC*32];
        #pragma unroll
        for (int pl = 0; pl < 16; pl++)
            acc[pl] += w0*Rs[na][pl] + w1*Rs[na][pl+1] + w2*Rs[na][pl+2];
    }

    float sd  = g_std [b*CINC + c];
    float mnv = g_mean[b*CINC + c];
    float db  = dec_b[c];
    #pragma unroll
    for (int pl = 0; pl < 16; pl++) {
        int p = p0 + pl;
        if (p < 511) {
            int t = p*32 + r;
            out[((size_t)b*CINC + c)*TT + t] = (acc[pl] + db)*sd + mnv;
        }
    }
}

// ---------------- finalize scalars ----------------
__global__ void k_final(float* __restrict__ out, int out_size) {
    if (blockIdx.x != 0 || threadIdx.x != 0) return;
    float tot = 0.f;
    const float cnt[3] = { (float)(NB*NAC*(LL/4)), (float)(NB*NAC*(LL/2)), (float)(NB*NAC*LL) };
    for (int sIdx = 0; sIdx < 3; sIdx++) {
        float ssum = 0.f;
        for (int i = 0; i < 512; i++) ssum += g_part[sIdx*512 + i];
        tot += ssum / cnt[sIdx];
    }
    if (out_size > NOUT)     out[NOUT]     = 0.f;
    if (out_size > NOUT + 1) out[NOUT + 1] = tot * 0.01f;
}

// ---------------- launch ----------------
extern "C" void kernel_launch(void* const* d_in, const int* in_sizes, int n_in,
                              void* d_out, int out_size) {
    const float* x        = (const float*)d_in[0];
    const float* stem_w1  = (const float*)d_in[1];
    const float* stem_b1  = (const float*)d_in[2];
    const float* stem_w2  = (const float*)d_in[3];
    const float* stem_b2  = (const float*)d_in[4];
    const float* stem_sc  = (const float*)d_in[5];
    const float* shapelet = (const float*)d_in[6];
    const float* dec_w    = (const float*)d_in[7];
    const float* dec_b    = (const float*)d_in[8];
    float* out = (float*)d_out;

    const int SM4 = (NAC*(17+65) + 17*NAC) * (int)sizeof(float);  // 50688
    const int SM2 = (NAC*(33+65) + 33*NAC) * (int)sizeof(float);  // 67072
    const int SM1 = (NAC*(64+65) + 64*NAC) * (int)sizeof(float);  // 98816
    const int SMEM_STEM = (CINC*594*2 + 64*68 + 4*64*SL + 64*SL) * (int)sizeof(float); // 94912
    cudaFuncSetAttribute(k_fconv<4,17>, cudaFuncAttributeMaxDynamicSharedMemorySize, SM4);
    cudaFuncSetAttribute(k_fconv<2,33>, cudaFuncAttributeMaxDynamicSharedMemorySize, SM2);
    cudaFuncSetAttribute(k_fconv<1,64>, cudaFuncAttributeMaxDynamicSharedMemorySize, SM1);
    cudaFuncSetAttribute(k_stem, cudaFuncAttributeMaxDynamicSharedMemorySize, SMEM_STEM);

    k_meanstd<<<NB*CINC, 256>>>(x);
    k_prep<<<NAC, 256>>>(shapelet);
    k_wstem<<<(CINC*64*64 + 255)/256, 256>>>(stem_w1);
    k_fold<<<(NAC*3*CINC*32 + 255)/256, 256>>>(dec_w);
    k_stem<<<dim3(LL/SL, NB), 256, SMEM_STEM>>>(x, stem_b1, stem_w2, stem_b2, stem_sc);

    // scale 4 (first: residual = z_raw, R = rec)
    k_pool<<<512, 256>>>(4, 1, 0);
    k_fconv<4,17><<<dim3(8, NB), 256, SM4>>>(1);
    // scale 2
    k_pool<<<512, 256>>>(2, 0, 1);
    k_fconv<2,33><<<dim3(8, NB), 256, SM2>>>(0);
    // scale 1
    k_pool<<<512, 256>>>(1, 0, 2);
    k_fconv<1,64><<<dim3(8, NB), 256, SM1>>>(0);

    k_dec<<<dim3(32, NB), 384>>>(dec_b, out);
    k_final<<<1, 32>>>(out, out_size);
}